// round 1
// baseline (speedup 1.0000x reference)
#include <cuda_runtime.h>
#include <math.h>

#define NCLS   80
#define CH     85          // 5 + NCLS
#define NBOX   70
#define NBATCH 16
#define INV_IN2 (1.0f/(608.0f*608.0f))   // input_size = stride*S = 608 for all scales
#define FOUR_OVER_PI2 0.40528473456935109f

// global fp64 accumulators: [0]=ciou, [1]=conf, [2]=prob
__device__ double g_acc[3];

__constant__ float c_anch[3][6] = {
    { 12.f,  16.f,  19.f,  36.f,  40.f,  28.f},   // stride 8  (sbbox)
    { 36.f,  75.f,  76.f,  55.f,  72.f, 146.f},   // stride 16 (mbbox)
    {142.f, 110.f, 192.f, 243.f, 459.f, 401.f}    // stride 32 (lbbox)
};

__device__ __forceinline__ float softplusf(float x) {
    // log(1+e^x) = max(x,0) + log1p(e^-|x|)
    return fmaxf(x, 0.f) + __logf(1.f + __expf(-fabsf(x)));
}

__device__ __forceinline__ float sigmoidf(float x) {
    return __fdividef(1.f, 1.f + __expf(-x));
}

__global__ void zero_kernel() {
    if (threadIdx.x < 3) g_acc[threadIdx.x] = 0.0;
}

__global__ void finalize_kernel(float* out) {
    double ci = g_acc[0] * (1.0 / NBATCH);
    double cf = g_acc[1] * (1.0 / NBATCH);
    double pr = g_acc[2] * (1.0 / NBATCH);
    out[0] = (float)(ci + cf + pr);
    out[1] = (float)ci;
    out[2] = (float)cf;
    out[3] = (float)pr;
}

__global__ void __launch_bounds__(256)
yolo_loss_kernel(const float* __restrict__ conv,
                 const float* __restrict__ label,
                 const float* __restrict__ bboxes,
                 int S, float stride, int scale_id)
{
    // Precomputed true-bbox corners + areas for ALL batches (SoA, broadcast-read)
    __shared__ float s_x1[NBATCH*NBOX], s_y1[NBATCH*NBOX];
    __shared__ float s_x2[NBATCH*NBOX], s_y2[NBATCH*NBOX];
    __shared__ float s_ar[NBATCH*NBOX];
    __shared__ float rbuf[3][8];

    for (int t = threadIdx.x; t < NBATCH*NBOX; t += blockDim.x) {
        float4 v = *reinterpret_cast<const float4*>(bboxes + (size_t)t*4);
        s_x1[t] = v.x - 0.5f*v.z;
        s_y1[t] = v.y - 0.5f*v.w;
        s_x2[t] = v.x + 0.5f*v.z;
        s_y2[t] = v.y + 0.5f*v.w;
        s_ar[t] = v.z * v.w;
    }
    __syncthreads();

    const int ncell = NBATCH * S * S * 3;
    const int idx = blockIdx.x * blockDim.x + threadIdx.x;

    float tc = 0.f, tf = 0.f, tp = 0.f;

    if (idx < ncell) {
        int a = idx % 3;
        int r = idx / 3;
        int j = r % S; r /= S;
        int i = r % S;
        int b = r / S;

        const float* cv = conv  + (size_t)idx * CH;
        const float* lb = label + (size_t)idx * CH;

        float dx = cv[0], dy = cv[1], dw = cv[2], dh = cv[3], dc = cv[4];
        float lx = lb[0], ly = lb[1], lw = lb[2], lh = lb[3], resp = lb[4];

        float aw = c_anch[scale_id][a*2 + 0];
        float ah = c_anch[scale_id][a*2 + 1];

        // decode
        float px = (sigmoidf(dx) + (float)j) * stride;
        float py = (sigmoidf(dy) + (float)i) * stride;
        float pw = __expf(dw) * aw;
        float ph = __expf(dh) * ah;

        // corners (wh >= 0 for both pred and label, so corners are ordered)
        float px1 = px - 0.5f*pw, py1 = py - 0.5f*ph;
        float px2 = px + 0.5f*pw, py2 = py + 0.5f*ph;
        float lx1 = lx - 0.5f*lw, ly1 = ly - 0.5f*lh;
        float lx2 = lx + 0.5f*lw, ly2 = ly + 0.5f*lh;

        // ----- CIoU vs label -----
        float areap = (px2 - px1) * (py2 - py1);
        float areal = (lx2 - lx1) * (ly2 - ly1);
        float iw = fmaxf(fminf(px2, lx2) - fmaxf(px1, lx1), 0.f);
        float ih = fmaxf(fminf(py2, ly2) - fmaxf(py1, ly1), 0.f);
        float inter = iw * ih;
        float uni = areap + areal - inter;
        float iou = __fdividef(inter, uni + 1e-9f);

        float ew = fmaxf(px2, lx2) - fminf(px1, lx1);
        float eh = fmaxf(py2, ly2) - fminf(py1, ly1);
        float c2 = ew*ew + eh*eh;
        float ddx = px - lx, ddy = py - ly;
        float p2 = ddx*ddx + ddy*ddy;

        float at = atanf(__fdividef(pw, ph + 1e-9f)) -
                   atanf(__fdividef(lw, lh + 1e-9f));
        float v  = FOUR_OVER_PI2 * at * at;
        float alpha = __fdividef(v, 1.f - iou + v);
        float ciou = iou - __fdividef(p2, c2) - alpha * v;

        tc = resp * (2.f - lw*lh*INV_IN2) * (1.f - ciou);

        // ----- background gate: max IoU vs 70 true boxes < 0.5 -----
        // iou_k < 0.5  <=>  inter_k/(pa + ba_k - inter_k) < 0.5  <=>  3*inter_k < pa + ba_k
        float pa = pw * ph;                 // reference bbox_iou uses w*h directly
        const int bo = b * NBOX;
        float m = -1e30f;
        #pragma unroll 7
        for (int k = 0; k < NBOX; k++) {
            float bw = fmaxf(fminf(px2, s_x2[bo+k]) - fmaxf(px1, s_x1[bo+k]), 0.f);
            float bh = fmaxf(fminf(py2, s_y2[bo+k]) - fmaxf(py1, s_y1[bo+k]), 0.f);
            float it = bw * bh;
            float s  = pa + s_ar[bo+k];
            m = fmaxf(m, __fmaf_rn(3.f, it, -s));
        }

        // ----- conf loss -----
        // pos = resp * softplus(-dc) = resp*(sp - dc); neg = bgd*(1-resp)*softplus(dc)
        float spc = softplusf(dc);
        tf = resp * (spc - dc);
        if (m < 0.f) tf += (1.f - resp) * spc;

        // ----- prob (class BCE) loss -----
        // lp*(-log s(x)) + (1-lp)*(-log(1-s(x))) = softplus(x) - lp*x
        float ps = 0.f;
        #pragma unroll 4
        for (int c = 0; c < NCLS; c++) {
            float x  = cv[5 + c];
            float lp = lb[5 + c];
            ps += softplusf(x) - lp * x;
        }
        tp = resp * ps;
    }

    // ----- block reduction -> fp64 atomic -----
    const unsigned mask = 0xffffffffu;
    #pragma unroll
    for (int off = 16; off; off >>= 1) {
        tc += __shfl_down_sync(mask, tc, off);
        tf += __shfl_down_sync(mask, tf, off);
        tp += __shfl_down_sync(mask, tp, off);
    }
    int wid = threadIdx.x >> 5, lane = threadIdx.x & 31;
    if (lane == 0) { rbuf[0][wid] = tc; rbuf[1][wid] = tf; rbuf[2][wid] = tp; }
    __syncthreads();
    if (threadIdx.x == 0) {
        float sc = 0.f, sf = 0.f, sp = 0.f;
        #pragma unroll
        for (int w = 0; w < 8; w++) { sc += rbuf[0][w]; sf += rbuf[1][w]; sp += rbuf[2][w]; }
        atomicAdd(&g_acc[0], (double)sc);
        atomicAdd(&g_acc[1], (double)sf);
        atomicAdd(&g_acc[2], (double)sp);
    }
}

extern "C" void kernel_launch(void* const* d_in, const int* in_sizes, int n_in,
                              void* d_out, int out_size)
{
    const float* conv_l = (const float*)d_in[0];   // (16,19,19,255)
    const float* conv_m = (const float*)d_in[1];   // (16,38,38,255)
    const float* conv_s = (const float*)d_in[2];   // (16,76,76,255)
    const float* lab_s  = (const float*)d_in[3];   // (16,76,76,3,85)
    const float* lab_m  = (const float*)d_in[4];   // (16,38,38,3,85)
    const float* lab_l  = (const float*)d_in[5];   // (16,19,19,3,85)
    const float* bb     = (const float*)d_in[6];   // (16,70,4)

    zero_kernel<<<1, 32>>>();

    {
        int ncell = NBATCH * 76 * 76 * 3;
        yolo_loss_kernel<<<(ncell + 255) / 256, 256>>>(conv_s, lab_s, bb, 76, 8.f, 0);
    }
    {
        int ncell = NBATCH * 38 * 38 * 3;
        yolo_loss_kernel<<<(ncell + 255) / 256, 256>>>(conv_m, lab_m, bb, 38, 16.f, 1);
    }
    {
        int ncell = NBATCH * 19 * 19 * 3;
        yolo_loss_kernel<<<(ncell + 255) / 256, 256>>>(conv_l, lab_l, bb, 19, 32.f, 2);
    }

    finalize_kernel<<<1, 1>>>((float*)d_out);
}

// round 2
// speedup vs baseline: 1.8250x; 1.8250x over previous
#include <cuda_runtime.h>
#include <math.h>

#define NCLS   80
#define CH     85          // 5 + NCLS
#define NBOX   70
#define NBATCH 16
#define CPB    256         // cells per block
#define INV_IN2 (1.0f/(608.0f*608.0f))

// global fp64 accumulators: [0]=ciou, [1]=conf, [2]=prob
__device__ double g_acc[3];

__constant__ float c_anch[3][6] = {
    { 12.f,  16.f,  19.f,  36.f,  40.f,  28.f},   // stride 8  (sbbox)
    { 36.f,  75.f,  76.f,  55.f,  72.f, 146.f},   // stride 16 (mbbox)
    {142.f, 110.f, 192.f, 243.f, 459.f, 401.f}    // stride 32 (lbbox)
};

__device__ __forceinline__ float softplusf(float x) {
    // log(1+e^x) = max(x,0) + log(1 + e^-|x|)
    return fmaxf(x, 0.f) + __logf(1.f + __expf(-fabsf(x)));
}

__device__ __forceinline__ float sigmoidf(float x) {
    return __fdividef(1.f, 1.f + __expf(-x));
}

__global__ void zero_kernel() {
    if (threadIdx.x < 3) g_acc[threadIdx.x] = 0.0;
}

__global__ void finalize_kernel(float* out) {
    double ci = g_acc[0] * (1.0 / NBATCH);
    double cf = g_acc[1] * (1.0 / NBATCH);
    double pr = g_acc[2] * (1.0 / NBATCH);
    out[0] = (float)(ci + cf + pr);
    out[1] = (float)ci;
    out[2] = (float)cf;
    out[3] = (float)pr;
}

template<int S, int STRIDE, int SCALE>
__global__ void __launch_bounds__(CPB)
yolo_kernel(const float* __restrict__ conv,
            const float* __restrict__ label,
            const float* __restrict__ bboxes)
{
    constexpr int NCELL = NBATCH * S * S * 3;

    __shared__ float4 s_box[NBATCH*NBOX];   // x1,y1,x2,y2
    __shared__ float  s_ar [NBATCH*NBOX];   // w*h
    __shared__ float  rbuf[3][CPB/32];

    const int tid = threadIdx.x;

    // stage true-bbox corners + areas (all batches)
    for (int t = tid; t < NBATCH*NBOX; t += CPB) {
        float4 v = __ldg(reinterpret_cast<const float4*>(bboxes) + t);
        s_box[t] = make_float4(v.x - 0.5f*v.z, v.y - 0.5f*v.w,
                               v.x + 0.5f*v.z, v.y + 0.5f*v.w);
        s_ar[t]  = v.z * v.w;
    }
    __syncthreads();

    const int cellBase = blockIdx.x * CPB;
    const int cells    = min(CPB, NCELL - cellBase);

    // ===== Phase 1: coalesced float4 streaming BCE over this block's chunk =====
    // cells*CH is always divisible by 4 (cells % 4 == 0 for all blocks here).
    const float4* __restrict__ cv4 = reinterpret_cast<const float4*>(conv  + (size_t)cellBase * CH);
    const float4* __restrict__ lb4 = reinterpret_cast<const float4*>(label + (size_t)cellBase * CH);
    const float*  __restrict__ lbF = label + (size_t)cellBase * CH;

    const int nf4 = cells * CH / 4;
    float ps = 0.f;

    for (int t = tid; t < nf4; t += CPB) {
        const int e  = 4 * t;
        const int cl = e / CH;          // local cell within chunk
        const int c0 = e - cl * CH;     // channel of component 0

        float4 x  = __ldg(cv4 + t);
        float4 lp = __ldg(lb4 + t);
        float  resp = __ldg(lbF + cl * CH + 4);

        // Components that wrap past CH land on channels 0..2 of the next
        // cell -> excluded by (c0+i < CH). Channels <5 excluded too, so all
        // contributing components share this cell's resp.
        float acc = 0.f;
        if (c0 + 0 >= 5 && c0 + 0 < CH) acc += softplusf(x.x) - lp.x * x.x;
        if (c0 + 1 >= 5 && c0 + 1 < CH) acc += softplusf(x.y) - lp.y * x.y;
        if (c0 + 2 >= 5 && c0 + 2 < CH) acc += softplusf(x.z) - lp.z * x.z;
        if (c0 + 3 >= 5 && c0 + 3 < CH) acc += softplusf(x.w) - lp.w * x.w;
        ps += resp * acc;
    }

    // ===== Phase 2: per-cell ciou + conf (fields 0..4, L1/L2 hits) =====
    float tc = 0.f, tf = 0.f;

    if (tid < cells) {
        const int idx = cellBase + tid;
        int a = idx % 3;
        int r = idx / 3;
        int j = r % S; r /= S;
        int i = r % S;
        int b = r / S;

        const float* cv = conv  + (size_t)idx * CH;
        const float* lb = label + (size_t)idx * CH;

        float dx = __ldg(cv+0), dy = __ldg(cv+1), dw = __ldg(cv+2),
              dh = __ldg(cv+3), dc = __ldg(cv+4);
        float lx = __ldg(lb+0), ly = __ldg(lb+1), lw = __ldg(lb+2),
              lh = __ldg(lb+3), resp = __ldg(lb+4);

        float aw = c_anch[SCALE][a*2 + 0];
        float ah = c_anch[SCALE][a*2 + 1];

        // decode
        float px = (sigmoidf(dx) + (float)j) * (float)STRIDE;
        float py = (sigmoidf(dy) + (float)i) * (float)STRIDE;
        float pw = __expf(dw) * aw;
        float ph = __expf(dh) * ah;

        float px1 = px - 0.5f*pw, py1 = py - 0.5f*ph;
        float px2 = px + 0.5f*pw, py2 = py + 0.5f*ph;
        float lx1 = lx - 0.5f*lw, ly1 = ly - 0.5f*lh;
        float lx2 = lx + 0.5f*lw, ly2 = ly + 0.5f*lh;

        // ----- CIoU vs label -----
        float areap = (px2 - px1) * (py2 - py1);
        float areal = (lx2 - lx1) * (ly2 - ly1);
        float iw = fmaxf(fminf(px2, lx2) - fmaxf(px1, lx1), 0.f);
        float ih = fmaxf(fminf(py2, ly2) - fmaxf(py1, ly1), 0.f);
        float inter = iw * ih;
        float uni   = areap + areal - inter;
        float iou   = __fdividef(inter, uni + 1e-9f);

        float ew = fmaxf(px2, lx2) - fminf(px1, lx1);
        float eh = fmaxf(py2, ly2) - fminf(py1, ly1);
        float c2 = ew*ew + eh*eh;
        float ddx = px - lx, ddy = py - ly;
        float p2 = ddx*ddx + ddy*ddy;

        const float FOUR_OVER_PI2 = 0.40528473456935109f;
        float at = atanf(__fdividef(pw, ph + 1e-9f)) -
                   atanf(__fdividef(lw, lh + 1e-9f));
        float v     = FOUR_OVER_PI2 * at * at;
        float alpha = __fdividef(v, 1.f - iou + v);
        float ciou  = iou - __fdividef(p2, c2) - alpha * v;

        tc = resp * (2.f - lw*lh*INV_IN2) * (1.f - ciou);

        // ----- background gate: max IoU vs 70 true boxes < 0.5 -----
        // iou_k < 0.5 <=> 3*inter_k < pa + ar_k <=> 3*inter_k - ar_k < pa
        float pa = pw * ph;
        const float4* bptr = s_box + b * NBOX;
        const float*  aptr = s_ar  + b * NBOX;
        float m = -1e30f;
        #pragma unroll 5
        for (int k = 0; k < NBOX; k++) {
            float4 bx = bptr[k];
            float bw = fmaxf(fminf(px2, bx.z) - fmaxf(px1, bx.x), 0.f);
            float bh = fmaxf(fminf(py2, bx.w) - fmaxf(py1, bx.y), 0.f);
            m = fmaxf(m, __fmaf_rn(3.f, bw * bh, -aptr[k]));
        }

        // ----- conf loss -----
        float spc = softplusf(dc);
        tf = resp * (spc - dc);
        if (m < pa) tf += (1.f - resp) * spc;
    }

    // ===== block reduction -> fp64 atomics =====
    const unsigned mask = 0xffffffffu;
    #pragma unroll
    for (int off = 16; off; off >>= 1) {
        tc += __shfl_down_sync(mask, tc, off);
        tf += __shfl_down_sync(mask, tf, off);
        ps += __shfl_down_sync(mask, ps, off);
    }
    int wid = tid >> 5, lane = tid & 31;
    if (lane == 0) { rbuf[0][wid] = tc; rbuf[1][wid] = tf; rbuf[2][wid] = ps; }
    __syncthreads();
    if (tid == 0) {
        float sc = 0.f, sf = 0.f, sp = 0.f;
        #pragma unroll
        for (int w = 0; w < CPB/32; w++) {
            sc += rbuf[0][w]; sf += rbuf[1][w]; sp += rbuf[2][w];
        }
        atomicAdd(&g_acc[0], (double)sc);
        atomicAdd(&g_acc[1], (double)sf);
        atomicAdd(&g_acc[2], (double)sp);
    }
}

extern "C" void kernel_launch(void* const* d_in, const int* in_sizes, int n_in,
                              void* d_out, int out_size)
{
    const float* conv_l = (const float*)d_in[0];   // (16,19,19,255)
    const float* conv_m = (const float*)d_in[1];   // (16,38,38,255)
    const float* conv_s = (const float*)d_in[2];   // (16,76,76,255)
    const float* lab_s  = (const float*)d_in[3];   // (16,76,76,3,85)
    const float* lab_m  = (const float*)d_in[4];   // (16,38,38,3,85)
    const float* lab_l  = (const float*)d_in[5];   // (16,19,19,3,85)
    const float* bb     = (const float*)d_in[6];   // (16,70,4)

    zero_kernel<<<1, 32>>>();

    {
        constexpr int ncell = NBATCH * 76 * 76 * 3;
        yolo_kernel<76, 8, 0><<<(ncell + CPB - 1) / CPB, CPB>>>(conv_s, lab_s, bb);
    }
    {
        constexpr int ncell = NBATCH * 38 * 38 * 3;
        yolo_kernel<38, 16, 1><<<(ncell + CPB - 1) / CPB, CPB>>>(conv_m, lab_m, bb);
    }
    {
        constexpr int ncell = NBATCH * 19 * 19 * 3;
        yolo_kernel<19, 32, 2><<<(ncell + CPB - 1) / CPB, CPB>>>(conv_l, lab_l, bb);
    }

    finalize_kernel<<<1, 1>>>((float*)d_out);
}

// round 3
// speedup vs baseline: 3.1994x; 1.7531x over previous
#include <cuda_runtime.h>
#include <math.h>

#define NCLS   80
#define CH     85          // 5 + NCLS
#define NBOX   70
#define NBATCH 16
#define CPB    256         // cells per block
#define INV_IN2 (1.0f/(608.0f*608.0f))

#define CELLS_S (NBATCH*76*76*3)   // 277248
#define CELLS_M (NBATCH*38*38*3)   //  69312
#define CELLS_L (NBATCH*19*19*3)   //  17328
#define BLKS_S  ((CELLS_S + CPB - 1) / CPB)   // 1083
#define BLKS_M  ((CELLS_M + CPB - 1) / CPB)   //  271
#define BLKS_L  ((CELLS_L + CPB - 1) / CPB)   //   68

__device__ double g_acc[3];

__constant__ float c_anch[3][6] = {
    { 12.f,  16.f,  19.f,  36.f,  40.f,  28.f},   // stride 8  (sbbox)
    { 36.f,  75.f,  76.f,  55.f,  72.f, 146.f},   // stride 16 (mbbox)
    {142.f, 110.f, 192.f, 243.f, 459.f, 401.f}    // stride 32 (lbbox)
};

__device__ __forceinline__ float ex2(float x) {
    float r; asm("ex2.approx.ftz.f32 %0, %1;" : "=f"(r) : "f"(x)); return r;
}
__device__ __forceinline__ float lg2(float x) {
    float r; asm("lg2.approx.ftz.f32 %0, %1;" : "=f"(r) : "f"(x)); return r;
}
#define L2E 1.4426950408889634f
#define LN2 0.6931471805599453f

__device__ __forceinline__ float softplusf(float x) {
    return fmaxf(x, 0.f) + LN2 * lg2(1.f + ex2(-fabsf(x) * L2E));
}
__device__ __forceinline__ float sigmoidf(float x) {
    return __fdividef(1.f, 1.f + ex2(-x * L2E));
}

__global__ void zero_kernel() {
    if (threadIdx.x < 3) g_acc[threadIdx.x] = 0.0;
}

__global__ void finalize_kernel(float* out) {
    double ci = g_acc[0] * (1.0 / NBATCH);
    double cf = g_acc[1] * (1.0 / NBATCH);
    double pr = g_acc[2] * (1.0 / NBATCH);
    out[0] = (float)(ci + cf + pr);
    out[1] = (float)ci;
    out[2] = (float)cf;
    out[3] = (float)pr;
}

template<int S, int STRIDE, int SCALE, int NCELL>
__device__ __forceinline__ void process_scale(
    const float* __restrict__ conv,
    const float* __restrict__ label,
    const float4* __restrict__ s_box,
    const float*  __restrict__ s_ar,
    int sblk, float& tc, float& tf, float& ps)
{
    const int tid      = threadIdx.x;
    const int cellBase = sblk * CPB;
    const int cells    = min(CPB, NCELL - cellBase);   // always multiple of 16

    // ===== Phase 1: coalesced float4 streaming class-BCE =====
    const float4* __restrict__ cv4 = reinterpret_cast<const float4*>(conv  + (size_t)cellBase * CH);
    const float4* __restrict__ lb4 = reinterpret_cast<const float4*>(label + (size_t)cellBase * CH);
    const float*  __restrict__ lbF = label + (size_t)cellBase * CH;

    const int nf4 = cells * CH / 4;

    for (int t = tid; t < nf4; t += CPB) {
        const int e  = 4 * t;
        const int cl = e / CH;
        const int c0 = e - cl * CH;     // channel of component 0 (0..84)

        float4 x  = __ldg(cv4 + t);
        float4 lp = __ldg(lb4 + t);
        float  resp = __ldg(lbF + cl * CH + 4);

        // channel masks: active iff 5 <= c0+i <= 84 (wrap comps land on
        // next cell's ch 0..2 -> masked; same-cell so one resp works)
        bool m0 = (c0 >= 5);
        bool m1 = (c0 >= 4) & (c0 <= 83);
        bool m2 = (c0 >= 3) & (c0 <= 82);
        bool m3 = (c0 >= 2) & (c0 <= 81);

        // t_i = e^{-|x_i|}, masked to 0 (so 1+t = 1 contributes nothing)
        float t0 = m0 ? ex2(-fabsf(x.x) * L2E) : 0.f;
        float t1 = m1 ? ex2(-fabsf(x.y) * L2E) : 0.f;
        float t2 = m2 ? ex2(-fabsf(x.z) * L2E) : 0.f;
        float t3 = m3 ? ex2(-fabsf(x.w) * L2E) : 0.f;

        // one LG2 per 4 classes: sum log1p(t_i) = log(prod (1+t_i))
        float p = (1.f + t0) * (1.f + t1) * (1.f + t2) * (1.f + t3);
        float lsum = LN2 * lg2(p);

        float summax = (m0 ? fmaxf(x.x, 0.f) : 0.f)
                     + (m1 ? fmaxf(x.y, 0.f) : 0.f)
                     + (m2 ? fmaxf(x.z, 0.f) : 0.f)
                     + (m3 ? fmaxf(x.w, 0.f) : 0.f);

        float dot = (m0 ? lp.x : 0.f) * x.x
                  + (m1 ? lp.y : 0.f) * x.y
                  + (m2 ? lp.z : 0.f) * x.z
                  + (m3 ? lp.w : 0.f) * x.w;

        ps += resp * (summax + lsum - dot);
    }

    // ===== Phase 2: per-cell ciou + conf (L1/L2-resident re-reads) =====
    if (tid < cells) {
        const int idx = cellBase + tid;
        int a = idx % 3;
        int r = idx / 3;
        int j = r % S; r /= S;
        int i = r % S;
        int b = r / S;

        const float* cv = conv  + (size_t)idx * CH;
        const float* lb = label + (size_t)idx * CH;

        float dx = __ldg(cv+0), dy = __ldg(cv+1), dw = __ldg(cv+2),
              dh = __ldg(cv+3), dc = __ldg(cv+4);
        float lx = __ldg(lb+0), ly = __ldg(lb+1), lw = __ldg(lb+2),
              lh = __ldg(lb+3), resp = __ldg(lb+4);

        float aw = c_anch[SCALE][a*2 + 0];
        float ah = c_anch[SCALE][a*2 + 1];

        float px = (sigmoidf(dx) + (float)j) * (float)STRIDE;
        float py = (sigmoidf(dy) + (float)i) * (float)STRIDE;
        float pw = ex2(dw * L2E) * aw;
        float ph = ex2(dh * L2E) * ah;

        float px1 = px - 0.5f*pw, py1 = py - 0.5f*ph;
        float px2 = px + 0.5f*pw, py2 = py + 0.5f*ph;
        float lx1 = lx - 0.5f*lw, ly1 = ly - 0.5f*lh;
        float lx2 = lx + 0.5f*lw, ly2 = ly + 0.5f*lh;

        float areap = (px2 - px1) * (py2 - py1);
        float areal = (lx2 - lx1) * (ly2 - ly1);
        float iw = fmaxf(fminf(px2, lx2) - fmaxf(px1, lx1), 0.f);
        float ih = fmaxf(fminf(py2, ly2) - fmaxf(py1, ly1), 0.f);
        float inter = iw * ih;
        float uni   = areap + areal - inter;
        float iou   = __fdividef(inter, uni + 1e-9f);

        float ew = fmaxf(px2, lx2) - fminf(px1, lx1);
        float eh = fmaxf(py2, ly2) - fminf(py1, ly1);
        float c2 = ew*ew + eh*eh;
        float ddx = px - lx, ddy = py - ly;
        float p2 = ddx*ddx + ddy*ddy;

        const float FOUR_OVER_PI2 = 0.40528473456935109f;
        float at = atanf(__fdividef(pw, ph + 1e-9f)) -
                   atanf(__fdividef(lw, lh + 1e-9f));
        float v     = FOUR_OVER_PI2 * at * at;
        float alpha = __fdividef(v, 1.f - iou + v);
        float ciou  = iou - __fdividef(p2, c2) - alpha * v;

        tc = resp * (2.f - lw*lh*INV_IN2) * (1.f - ciou);

        // background gate: max IoU vs 70 boxes < 0.5 <=> 3*inter - ar_k < pa
        float pa = pw * ph;
        const float4* bptr = s_box + b * NBOX;
        const float*  aptr = s_ar  + b * NBOX;
        float m = -1e30f;
        #pragma unroll 5
        for (int k = 0; k < NBOX; k++) {
            float4 bx = bptr[k];
            float bw = fmaxf(fminf(px2, bx.z) - fmaxf(px1, bx.x), 0.f);
            float bh = fmaxf(fminf(py2, bx.w) - fmaxf(py1, bx.y), 0.f);
            m = fmaxf(m, __fmaf_rn(3.f, bw * bh, -aptr[k]));
        }

        float spc = softplusf(dc);
        tf = resp * (spc - dc);
        if (m < pa) tf += (1.f - resp) * spc;
    }
}

__global__ void __launch_bounds__(CPB)
yolo_fused_kernel(const float* __restrict__ conv_s, const float* __restrict__ lab_s,
                  const float* __restrict__ conv_m, const float* __restrict__ lab_m,
                  const float* __restrict__ conv_l, const float* __restrict__ lab_l,
                  const float* __restrict__ bboxes)
{
    __shared__ float4 s_box[NBATCH*NBOX];
    __shared__ float  s_ar [NBATCH*NBOX];
    __shared__ float  rbuf[3][CPB/32];

    const int tid = threadIdx.x;

    for (int t = tid; t < NBATCH*NBOX; t += CPB) {
        float4 v = __ldg(reinterpret_cast<const float4*>(bboxes) + t);
        s_box[t] = make_float4(v.x - 0.5f*v.z, v.y - 0.5f*v.w,
                               v.x + 0.5f*v.z, v.y + 0.5f*v.w);
        s_ar[t]  = v.z * v.w;
    }
    __syncthreads();

    float tc = 0.f, tf = 0.f, ps = 0.f;

    const int blk = blockIdx.x;
    if (blk < BLKS_S) {
        process_scale<76,  8, 0, CELLS_S>(conv_s, lab_s, s_box, s_ar, blk, tc, tf, ps);
    } else if (blk < BLKS_S + BLKS_M) {
        process_scale<38, 16, 1, CELLS_M>(conv_m, lab_m, s_box, s_ar, blk - BLKS_S, tc, tf, ps);
    } else {
        process_scale<19, 32, 2, CELLS_L>(conv_l, lab_l, s_box, s_ar, blk - BLKS_S - BLKS_M, tc, tf, ps);
    }

    // ===== block reduction -> fp64 atomics =====
    const unsigned mask = 0xffffffffu;
    #pragma unroll
    for (int off = 16; off; off >>= 1) {
        tc += __shfl_down_sync(mask, tc, off);
        tf += __shfl_down_sync(mask, tf, off);
        ps += __shfl_down_sync(mask, ps, off);
    }
    int wid = tid >> 5, lane = tid & 31;
    if (lane == 0) { rbuf[0][wid] = tc; rbuf[1][wid] = tf; rbuf[2][wid] = ps; }
    __syncthreads();
    if (tid == 0) {
        float sc = 0.f, sf = 0.f, sp = 0.f;
        #pragma unroll
        for (int w = 0; w < CPB/32; w++) {
            sc += rbuf[0][w]; sf += rbuf[1][w]; sp += rbuf[2][w];
        }
        atomicAdd(&g_acc[0], (double)sc);
        atomicAdd(&g_acc[1], (double)sf);
        atomicAdd(&g_acc[2], (double)sp);
    }
}

extern "C" void kernel_launch(void* const* d_in, const int* in_sizes, int n_in,
                              void* d_out, int out_size)
{
    const float* conv_l = (const float*)d_in[0];   // (16,19,19,255)
    const float* conv_m = (const float*)d_in[1];   // (16,38,38,255)
    const float* conv_s = (const float*)d_in[2];   // (16,76,76,255)
    const float* lab_s  = (const float*)d_in[3];   // (16,76,76,3,85)
    const float* lab_m  = (const float*)d_in[4];   // (16,38,38,3,85)
    const float* lab_l  = (const float*)d_in[5];   // (16,19,19,3,85)
    const float* bb     = (const float*)d_in[6];   // (16,70,4)

    zero_kernel<<<1, 32>>>();

    yolo_fused_kernel<<<BLKS_S + BLKS_M + BLKS_L, CPB>>>(
        conv_s, lab_s, conv_m, lab_m, conv_l, lab_l, bb);

    finalize_kernel<<<1, 1>>>((float*)d_out);
}